// round 2
// baseline (speedup 1.0000x reference)
#include <cuda_runtime.h>

// LinearViolationAdaption — GB300 sm_103a
//
// 256 independent problems (B*S), each: up to 51 iterations of
//   Ax ; viol = relu(Ax - b) ; if sum(viol) < DELTA stop ;
//   g = viol^T A ; x = relu(x - ALPHA/(1+SCALE*g) * g)
//
// Per-problem independence is exact (see analysis): inactive rows never change,
// clamp is a no-op (x >= 0 invariant), so global any()/early-stop coupling
// reduces to per-problem early exit.
//
// Design: persistent grid of 128 CTAs x 512 threads; CTA k handles problems
// k and k+128 (balanced, 2 each). Concurrent A working set = 128 MB ~= L2,
// so the second pass and all re-iterations hit L2; HBM reads A ~once.

#define LVA_ALPHA 0.005f
#define LVA_SCALE 0.001f
#define LVA_DELTA 0.1f
#define LVA_ITERS 51   // MAX_ITER + 1

#define LVA_N 512
#define LVA_M 512
#define LVA_NCTA 128
#define LVA_THREADS 512

__global__ void __launch_bounds__(LVA_THREADS, 1)
lva_kernel(const float* __restrict__ x_in,
           const float* __restrict__ A,
           const float* __restrict__ b,
           float* __restrict__ x_out,
           int nprob)
{
    __shared__ float x_sm[LVA_N];
    __shared__ float viol_sm[LVA_M];
    __shared__ float red_sm[16];
    __shared__ int   done_sm;

    const int tid  = threadIdx.x;
    const int warp = tid >> 5;
    const int lane = tid & 31;

    for (int p = blockIdx.x; p < nprob; p += gridDim.x) {
        const float* __restrict__ Ap = A + (size_t)p * LVA_M * LVA_N;
        const float* __restrict__ bp = b + (size_t)p * LVA_M;

        // load x for this problem into SMEM
        x_sm[tid] = x_in[(size_t)p * LVA_N + tid];
        if (tid == 0) done_sm = 0;
        __syncthreads();

        for (int it = 0; it < LVA_ITERS; ++it) {
            // ---------------- Pass 1: Ax, viol, sum(viol) ----------------
            // warp w handles rows m = w, w+16, ... (32 rows). Per row:
            // lane covers float4 chunks lane, lane+32, lane+64, lane+96
            // -> LDG.128 coalesced; x read as float4 from SMEM (no conflicts).
            float vsum = 0.0f;
            const float4* x4 = (const float4*)x_sm;
            for (int m = warp; m < LVA_M; m += 16) {
                const float4* __restrict__ row =
                    (const float4*)(Ap + (size_t)m * LVA_N);
                float acc = 0.0f;
                #pragma unroll
                for (int k = 0; k < 4; ++k) {
                    float4 a  = row[lane + 32 * k];
                    float4 xv = x4[lane + 32 * k];
                    acc += a.x * xv.x + a.y * xv.y + a.z * xv.z + a.w * xv.w;
                }
                // butterfly warp reduce
                #pragma unroll
                for (int off = 16; off; off >>= 1)
                    acc += __shfl_xor_sync(0xffffffffu, acc, off);
                if (lane == 0) {
                    float v = acc - bp[m];
                    v = v > 0.0f ? v : 0.0f;
                    viol_sm[m] = v;
                    vsum += v;
                }
            }
            if (lane == 0) red_sm[warp] = vsum;
            __syncthreads();
            if (tid == 0) {
                float t = 0.0f;
                #pragma unroll
                for (int w = 0; w < 16; ++w) t += red_sm[w];
                done_sm = (t < LVA_DELTA) ? 1 : 0;
            }
            __syncthreads();
            if (done_sm) break;   // row went inactive BEFORE this update

            // ---------------- Pass 2: g = viol^T A, x update ----------------
            // thread t owns column t: A[m*512 + t] is a coalesced 128B line
            // per warp per m; viol_sm[m] is an SMEM broadcast. Pass 1 just
            // streamed A, so these are L2 hits.
            float g = 0.0f;
            const float* __restrict__ col = Ap + tid;
            #pragma unroll 8
            for (int m = 0; m < LVA_M; ++m) {
                g += viol_sm[m] * col[(size_t)m * LVA_N];
            }
            float lr = LVA_ALPHA / (1.0f + LVA_SCALE * g);
            float xv = x_sm[tid] - lr * g;
            x_sm[tid] = xv > 0.0f ? xv : 0.0f;
            __syncthreads();
        }

        // write back final x (always — output buffer is poisoned)
        x_out[(size_t)p * LVA_N + tid] = x_sm[tid];
        __syncthreads();   // protect SMEM before next problem reuses it
    }
}

extern "C" void kernel_launch(void* const* d_in, const int* in_sizes, int n_in,
                              void* d_out, int out_size)
{
    const float* x = (const float*)d_in[0];   // [B,S,N]   = 131072 f32
    const float* A = (const float*)d_in[1];   // [B,S,M,N] = 67108864 f32
    const float* b = (const float*)d_in[2];   // [B,S,M]   = 131072 f32
    float* out = (float*)d_out;               // [B,S,N]

    int nprob = out_size / LVA_N;             // 256
    int ncta  = nprob < LVA_NCTA ? nprob : LVA_NCTA;

    lva_kernel<<<ncta, LVA_THREADS>>>(x, A, b, out, nprob);
}

// round 3
// speedup vs baseline: 3.6858x; 3.6858x over previous
#include <cuda_runtime.h>

// LinearViolationAdaption — GB300 sm_103a, round 2
//
// Fused single-pass iteration: while computing viol[m] = relu(A[m,:]·x - b[m])
// the A row sits in registers; after the warp butterfly-reduce broadcasts
// viol[m], the SAME registers feed g += viol[m]*A[m,:]. A is read once/iter.
//
// Concurrency capped at 96 CTAs (96 MB < 126 MB L2) so A stays L2-resident
// across all 51 iterations; an atomic work queue over the 256 problems keeps
// all CTAs busy despite uneven per-problem iteration counts.

#define LVA_ALPHA 0.005f
#define LVA_SCALE 0.001f
#define LVA_DELTA 0.1f
#define LVA_ITERS 51   // MAX_ITER + 1

#define LVA_N 512
#define LVA_M 512
#define LVA_NCTA 96
#define LVA_THREADS 512
#define LVA_NWARP (LVA_THREADS / 32)

__device__ int lva_work_ctr;

__global__ void lva_reset_kernel() { lva_work_ctr = 0; }

__global__ void __launch_bounds__(LVA_THREADS, 1)
lva_fused_kernel(const float* __restrict__ x_in,
                 const float* __restrict__ A,
                 const float* __restrict__ b,
                 float* __restrict__ x_out,
                 int nprob)
{
    __shared__ __align__(16) float x_sm[LVA_N];
    __shared__ float b_sm[LVA_M];
    __shared__ __align__(16) float g_sm[LVA_NWARP * LVA_N];   // 32 KB
    __shared__ float red_sm[LVA_NWARP];
    __shared__ int   done_sm;
    __shared__ int   prob_sm;

    const int tid  = threadIdx.x;
    const int warp = tid >> 5;
    const int lane = tid & 31;

    for (;;) {
        __syncthreads();   // protect SMEM + prob_sm from previous problem
        if (tid == 0) prob_sm = atomicAdd(&lva_work_ctr, 1);
        __syncthreads();
        const int p = prob_sm;
        if (p >= nprob) return;

        const float* __restrict__ Ap = A + (size_t)p * LVA_M * LVA_N;

        x_sm[tid] = x_in[(size_t)p * LVA_N + tid];
        b_sm[tid] = b[(size_t)p * LVA_M + tid];
        __syncthreads();

        // x chunk for this lane's columns, register-resident
        float4 xv0 = ((const float4*)x_sm)[lane];
        float4 xv1 = ((const float4*)x_sm)[lane + 32];
        float4 xv2 = ((const float4*)x_sm)[lane + 64];
        float4 xv3 = ((const float4*)x_sm)[lane + 96];

        for (int it = 0; it < LVA_ITERS; ++it) {
            float4 g0 = make_float4(0.f, 0.f, 0.f, 0.f);
            float4 g1 = g0, g2 = g0, g3 = g0;
            float vsum = 0.0f;

            // warp handles rows warp, warp+16, ... (32 rows)
            for (int m = warp; m < LVA_M; m += LVA_NWARP) {
                const float4* __restrict__ row =
                    (const float4*)(Ap + (size_t)m * LVA_N);
                // all 4 LDG.128 issued before use -> MLP 4
                float4 a0 = row[lane];
                float4 a1 = row[lane + 32];
                float4 a2 = row[lane + 64];
                float4 a3 = row[lane + 96];

                // dot(A[m,:], x) with 2 accumulator chains
                float acc0 = a0.x * xv0.x;
                float acc1 = a0.y * xv0.y;
                acc0 += a0.z * xv0.z;  acc1 += a0.w * xv0.w;
                acc0 += a1.x * xv1.x;  acc1 += a1.y * xv1.y;
                acc0 += a1.z * xv1.z;  acc1 += a1.w * xv1.w;
                acc0 += a2.x * xv2.x;  acc1 += a2.y * xv2.y;
                acc0 += a2.z * xv2.z;  acc1 += a2.w * xv2.w;
                acc0 += a3.x * xv3.x;  acc1 += a3.y * xv3.y;
                acc0 += a3.z * xv3.z;  acc1 += a3.w * xv3.w;
                float acc = acc0 + acc1;
                #pragma unroll
                for (int off = 16; off; off >>= 1)
                    acc += __shfl_xor_sync(0xffffffffu, acc, off);

                float v = acc - b_sm[m];
                v = v > 0.0f ? v : 0.0f;
                vsum += v;

                // g += viol[m] * A[m,:] — A rows still in registers
                g0.x += v * a0.x; g0.y += v * a0.y; g0.z += v * a0.z; g0.w += v * a0.w;
                g1.x += v * a1.x; g1.y += v * a1.y; g1.z += v * a1.z; g1.w += v * a1.w;
                g2.x += v * a2.x; g2.y += v * a2.y; g2.z += v * a2.z; g2.w += v * a2.w;
                g3.x += v * a3.x; g3.y += v * a3.y; g3.z += v * a3.z; g3.w += v * a3.w;
            }

            // stage per-warp g partials (STS.128, conflict-free)
            float4* gp = (float4*)(g_sm + warp * LVA_N);
            gp[lane]      = g0;
            gp[lane + 32] = g1;
            gp[lane + 64] = g2;
            gp[lane + 96] = g3;
            if (lane == 0) red_sm[warp] = vsum;   // vsum is lane-uniform
            __syncthreads();

            // column-tid g reduction across warps (stride 512 floats:
            // same bank per w, distinct banks across lanes -> conflict-free)
            float gt = 0.0f;
            #pragma unroll
            for (int w = 0; w < LVA_NWARP; ++w)
                gt += g_sm[w * LVA_N + tid];

            if (tid == 0) {
                float t = 0.0f;
                #pragma unroll
                for (int w = 0; w < LVA_NWARP; ++w) t += red_sm[w];
                done_sm = (t < LVA_DELTA) ? 1 : 0;
            }
            __syncthreads();
            if (done_sm) break;   // inactive BEFORE this update

            float lr = LVA_ALPHA / (1.0f + LVA_SCALE * gt);
            float xn = x_sm[tid] - lr * gt;
            x_sm[tid] = xn > 0.0f ? xn : 0.0f;
            __syncthreads();

            xv0 = ((const float4*)x_sm)[lane];
            xv1 = ((const float4*)x_sm)[lane + 32];
            xv2 = ((const float4*)x_sm)[lane + 64];
            xv3 = ((const float4*)x_sm)[lane + 96];
        }

        x_out[(size_t)p * LVA_N + tid] = x_sm[tid];
    }
}

extern "C" void kernel_launch(void* const* d_in, const int* in_sizes, int n_in,
                              void* d_out, int out_size)
{
    const float* x = (const float*)d_in[0];   // [B,S,N]
    const float* A = (const float*)d_in[1];   // [B,S,M,N]
    const float* b = (const float*)d_in[2];   // [B,S,M]
    float* out = (float*)d_out;               // [B,S,N]

    int nprob = out_size / LVA_N;             // 256
    int ncta  = nprob < LVA_NCTA ? nprob : LVA_NCTA;

    lva_reset_kernel<<<1, 1>>>();
    lva_fused_kernel<<<ncta, LVA_THREADS>>>(x, A, b, out, nprob);
}

// round 4
// speedup vs baseline: 4.6661x; 1.2660x over previous
#include <cuda_runtime.h>

// LinearViolationAdaption — GB300 sm_103a, round 3
//
// Same fused algorithm as R2 (A read once per iteration, L2-resident via
// 96-CTA cap + atomic work queue), restructured for latency hiding:
//  * 2 rows per inner body -> two interleaved independent SHFL butterflies
//    (~150 cyc / 2 rows instead of 130 cyc serial per row)
//  * depth-2 software pipeline on A row loads (16 LDG.128 in flight)
//    so the ~262-cyc L2 hit latency is covered by body compute.

#define LVA_ALPHA 0.005f
#define LVA_SCALE 0.001f
#define LVA_DELTA 0.1f
#define LVA_ITERS 51   // MAX_ITER + 1

#define LVA_N 512
#define LVA_M 512
#define LVA_NCTA 96
#define LVA_THREADS 512
#define LVA_NWARP (LVA_THREADS / 32)

__device__ int lva_work_ctr;

__global__ void lva_reset_kernel() { lva_work_ctr = 0; }

__global__ void __launch_bounds__(LVA_THREADS, 1)
lva_fused_kernel(const float* __restrict__ x_in,
                 const float* __restrict__ A,
                 const float* __restrict__ b,
                 float* __restrict__ x_out,
                 int nprob)
{
    __shared__ __align__(16) float x_sm[LVA_N];
    __shared__ float b_sm[LVA_M];
    __shared__ __align__(16) float g_sm[LVA_NWARP * LVA_N];   // 32 KB
    __shared__ float red_sm[LVA_NWARP];
    __shared__ int   done_sm;
    __shared__ int   prob_sm;

    const int tid  = threadIdx.x;
    const int warp = tid >> 5;
    const int lane = tid & 31;

    for (;;) {
        __syncthreads();   // protect SMEM + prob_sm from previous problem
        if (tid == 0) prob_sm = atomicAdd(&lva_work_ctr, 1);
        __syncthreads();
        const int p = prob_sm;
        if (p >= nprob) return;

        const float* __restrict__ Ap = A + (size_t)p * LVA_M * LVA_N;

        x_sm[tid] = x_in[(size_t)p * LVA_N + tid];
        b_sm[tid] = b[(size_t)p * LVA_M + tid];
        __syncthreads();

        // x chunk for this lane's columns, register-resident
        float4 xv0 = ((const float4*)x_sm)[lane];
        float4 xv1 = ((const float4*)x_sm)[lane + 32];
        float4 xv2 = ((const float4*)x_sm)[lane + 64];
        float4 xv3 = ((const float4*)x_sm)[lane + 96];

        for (int it = 0; it < LVA_ITERS; ++it) {
            float4 g0 = make_float4(0.f, 0.f, 0.f, 0.f);
            float4 g1 = g0, g2 = g0, g3 = g0;
            float vsum = 0.0f;

            // warp w owns rows w, w+16, ..., w+496 (32 rows), processed as
            // 16 bodies of 2 rows: (w + 32t, w + 32t + 16).
            // Depth-2 pipeline: cur = body t, nxt = body t+1.
            const float4* __restrict__ r0 =
                (const float4*)(Ap + (size_t)warp * LVA_N);
            const float4* __restrict__ r1 =
                (const float4*)(Ap + (size_t)(warp + 16) * LVA_N);

            float4 c0a = r0[lane], c0b = r0[lane + 32],
                   c0c = r0[lane + 64], c0d = r0[lane + 96];
            float4 c1a = r1[lane], c1b = r1[lane + 32],
                   c1c = r1[lane + 64], c1d = r1[lane + 96];

            for (int t = 0; t < 16; ++t) {
                const int mcur0 = warp + 32 * t;
                // prefetch body t+1 (last iter re-reads body 0, harmless)
                const int tn = (t < 15) ? t + 1 : 0;
                const float4* __restrict__ n0 =
                    (const float4*)(Ap + (size_t)(warp + 32 * tn) * LVA_N);
                const float4* __restrict__ n1 =
                    (const float4*)(Ap + (size_t)(warp + 32 * tn + 16) * LVA_N);
                float4 p0a = n0[lane], p0b = n0[lane + 32],
                       p0c = n0[lane + 64], p0d = n0[lane + 96];
                float4 p1a = n1[lane], p1b = n1[lane + 32],
                       p1c = n1[lane + 64], p1d = n1[lane + 96];

                // dot products: 4 independent FMA chains (2 per row)
                float a0 = c0a.x * xv0.x, a1 = c0a.y * xv0.y;
                float a2 = c1a.x * xv0.x, a3 = c1a.y * xv0.y;
                a0 += c0a.z * xv0.z;  a1 += c0a.w * xv0.w;
                a2 += c1a.z * xv0.z;  a3 += c1a.w * xv0.w;
                a0 += c0b.x * xv1.x;  a1 += c0b.y * xv1.y;
                a2 += c1b.x * xv1.x;  a3 += c1b.y * xv1.y;
                a0 += c0b.z * xv1.z;  a1 += c0b.w * xv1.w;
                a2 += c1b.z * xv1.z;  a3 += c1b.w * xv1.w;
                a0 += c0c.x * xv2.x;  a1 += c0c.y * xv2.y;
                a2 += c1c.x * xv2.x;  a3 += c1c.y * xv2.y;
                a0 += c0c.z * xv2.z;  a1 += c0c.w * xv2.w;
                a2 += c1c.z * xv2.z;  a3 += c1c.w * xv2.w;
                a0 += c0d.x * xv3.x;  a1 += c0d.y * xv3.y;
                a2 += c1d.x * xv3.x;  a3 += c1d.y * xv3.y;
                a0 += c0d.z * xv3.z;  a1 += c0d.w * xv3.w;
                a2 += c1d.z * xv3.z;  a3 += c1d.w * xv3.w;
                float d0 = a0 + a1;
                float d1 = a2 + a3;

                // two interleaved independent butterflies
                #pragma unroll
                for (int off = 16; off; off >>= 1) {
                    d0 += __shfl_xor_sync(0xffffffffu, d0, off);
                    d1 += __shfl_xor_sync(0xffffffffu, d1, off);
                }

                float v0 = d0 - b_sm[mcur0];
                float v1 = d1 - b_sm[mcur0 + 16];
                v0 = v0 > 0.0f ? v0 : 0.0f;
                v1 = v1 > 0.0f ? v1 : 0.0f;
                vsum += v0 + v1;

                // g += v0*A[m0,:] + v1*A[m1,:]  (A rows still in registers)
                g0.x += v0 * c0a.x + v1 * c1a.x;
                g0.y += v0 * c0a.y + v1 * c1a.y;
                g0.z += v0 * c0a.z + v1 * c1a.z;
                g0.w += v0 * c0a.w + v1 * c1a.w;
                g1.x += v0 * c0b.x + v1 * c1b.x;
                g1.y += v0 * c0b.y + v1 * c1b.y;
                g1.z += v0 * c0b.z + v1 * c1b.z;
                g1.w += v0 * c0b.w + v1 * c1b.w;
                g2.x += v0 * c0c.x + v1 * c1c.x;
                g2.y += v0 * c0c.y + v1 * c1c.y;
                g2.z += v0 * c0c.z + v1 * c1c.z;
                g2.w += v0 * c0c.w + v1 * c1c.w;
                g3.x += v0 * c0d.x + v1 * c1d.x;
                g3.y += v0 * c0d.y + v1 * c1d.y;
                g3.z += v0 * c0d.z + v1 * c1d.z;
                g3.w += v0 * c0d.w + v1 * c1d.w;

                // rotate pipeline
                c0a = p0a; c0b = p0b; c0c = p0c; c0d = p0d;
                c1a = p1a; c1b = p1b; c1c = p1c; c1d = p1d;
            }

            // stage per-warp g partials (STS.128, conflict-free)
            float4* gp = (float4*)(g_sm + warp * LVA_N);
            gp[lane]      = g0;
            gp[lane + 32] = g1;
            gp[lane + 64] = g2;
            gp[lane + 96] = g3;
            if (lane == 0) red_sm[warp] = vsum;   // vsum is lane-uniform
            __syncthreads();

            // column-tid g reduction across warps (conflict-free: stride 512)
            float gt = 0.0f;
            #pragma unroll
            for (int w = 0; w < LVA_NWARP; ++w)
                gt += g_sm[w * LVA_N + tid];

            if (tid == 0) {
                float s = 0.0f;
                #pragma unroll
                for (int w = 0; w < LVA_NWARP; ++w) s += red_sm[w];
                done_sm = (s < LVA_DELTA) ? 1 : 0;
            }
            __syncthreads();
            if (done_sm) break;   // inactive BEFORE this update

            float lr = LVA_ALPHA / (1.0f + LVA_SCALE * gt);
            float xn = x_sm[tid] - lr * gt;
            x_sm[tid] = xn > 0.0f ? xn : 0.0f;
            __syncthreads();

            xv0 = ((const float4*)x_sm)[lane];
            xv1 = ((const float4*)x_sm)[lane + 32];
            xv2 = ((const float4*)x_sm)[lane + 64];
            xv3 = ((const float4*)x_sm)[lane + 96];
        }

        x_out[(size_t)p * LVA_N + tid] = x_sm[tid];
    }
}

extern "C" void kernel_launch(void* const* d_in, const int* in_sizes, int n_in,
                              void* d_out, int out_size)
{
    const float* x = (const float*)d_in[0];   // [B,S,N]
    const float* A = (const float*)d_in[1];   // [B,S,M,N]
    const float* b = (const float*)d_in[2];   // [B,S,M]
    float* out = (float*)d_out;               // [B,S,N]

    int nprob = out_size / LVA_N;             // 256
    int ncta  = nprob < LVA_NCTA ? nprob : LVA_NCTA;

    lva_reset_kernel<<<1, 1>>>();
    lva_fused_kernel<<<ncta, LVA_THREADS>>>(x, A, b, out, nprob);
}

// round 9
// speedup vs baseline: 4.6940x; 1.0060x over previous
#include <cuda_runtime.h>

// LinearViolationAdaption — GB300 sm_103a, round 4
//
// R3 structure (fused single-read-of-A iteration, 96-CTA L2-resident cap,
// atomic work queue) with issue-count reductions:
//  * explicit ping-pong unroll-by-2 -> no pipeline-rotation register MOVs
//  * 2 barriers/iter instead of 3 (all threads recompute the done-flag from
//    red_sm broadcast reads; uniform branch)
//  * body loop kept rolled (fits L0 I$), cheap &15 index math

#define LVA_ALPHA 0.005f
#define LVA_SCALE 0.001f
#define LVA_DELTA 0.1f
#define LVA_ITERS 51   // MAX_ITER + 1

#define LVA_N 512
#define LVA_M 512
#define LVA_NCTA 96
#define LVA_THREADS 512
#define LVA_NWARP (LVA_THREADS / 32)

__device__ int lva_work_ctr;

__global__ void lva_reset_kernel() { lva_work_ctr = 0; }

struct Buf2 {
    float4 a0, a1, a2, a3;   // row m
    float4 b0, b1, b2, b3;   // row m+16

    __device__ __forceinline__ void load(const float* __restrict__ Ap,
                                         int m0, int lane) {
        const float4* __restrict__ p0 = (const float4*)(Ap + (size_t)m0 * LVA_N);
        const float4* __restrict__ p1 = (const float4*)(Ap + (size_t)(m0 + 16) * LVA_N);
        a0 = p0[lane]; a1 = p0[lane + 32]; a2 = p0[lane + 64]; a3 = p0[lane + 96];
        b0 = p1[lane]; b1 = p1[lane + 32]; b2 = p1[lane + 64]; b3 = p1[lane + 96];
    }
};

// process 2 rows held in buf: viol, vsum, g accumulation
__device__ __forceinline__ void body2(const Buf2& B, int m0,
                                      const float* __restrict__ b_sm,
                                      const float4& xv0, const float4& xv1,
                                      const float4& xv2, const float4& xv3,
                                      float4& g0, float4& g1,
                                      float4& g2, float4& g3,
                                      float& vsum)
{
    // 4 independent FMA chains (2 per row)
    float s0 = B.a0.x * xv0.x, s1 = B.a0.y * xv0.y;
    float s2 = B.b0.x * xv0.x, s3 = B.b0.y * xv0.y;
    s0 += B.a0.z * xv0.z;  s1 += B.a0.w * xv0.w;
    s2 += B.b0.z * xv0.z;  s3 += B.b0.w * xv0.w;
    s0 += B.a1.x * xv1.x;  s1 += B.a1.y * xv1.y;
    s2 += B.b1.x * xv1.x;  s3 += B.b1.y * xv1.y;
    s0 += B.a1.z * xv1.z;  s1 += B.a1.w * xv1.w;
    s2 += B.b1.z * xv1.z;  s3 += B.b1.w * xv1.w;
    s0 += B.a2.x * xv2.x;  s1 += B.a2.y * xv2.y;
    s2 += B.b2.x * xv2.x;  s3 += B.b2.y * xv2.y;
    s0 += B.a2.z * xv2.z;  s1 += B.a2.w * xv2.w;
    s2 += B.b2.z * xv2.z;  s3 += B.b2.w * xv2.w;
    s0 += B.a3.x * xv3.x;  s1 += B.a3.y * xv3.y;
    s2 += B.b3.x * xv3.x;  s3 += B.b3.y * xv3.y;
    s0 += B.a3.z * xv3.z;  s1 += B.a3.w * xv3.w;
    s2 += B.b3.z * xv3.z;  s3 += B.b3.w * xv3.w;
    float d0 = s0 + s1;
    float d1 = s2 + s3;

    // two interleaved independent butterflies
    #pragma unroll
    for (int off = 16; off; off >>= 1) {
        d0 += __shfl_xor_sync(0xffffffffu, d0, off);
        d1 += __shfl_xor_sync(0xffffffffu, d1, off);
    }

    float v0 = d0 - b_sm[m0];
    float v1 = d1 - b_sm[m0 + 16];
    v0 = v0 > 0.0f ? v0 : 0.0f;
    v1 = v1 > 0.0f ? v1 : 0.0f;
    vsum += v0 + v1;

    g0.x += v0 * B.a0.x + v1 * B.b0.x;
    g0.y += v0 * B.a0.y + v1 * B.b0.y;
    g0.z += v0 * B.a0.z + v1 * B.b0.z;
    g0.w += v0 * B.a0.w + v1 * B.b0.w;
    g1.x += v0 * B.a1.x + v1 * B.b1.x;
    g1.y += v0 * B.a1.y + v1 * B.b1.y;
    g1.z += v0 * B.a1.z + v1 * B.b1.z;
    g1.w += v0 * B.a1.w + v1 * B.b1.w;
    g2.x += v0 * B.a2.x + v1 * B.b2.x;
    g2.y += v0 * B.a2.y + v1 * B.b2.y;
    g2.z += v0 * B.a2.z + v1 * B.b2.z;
    g2.w += v0 * B.a2.w + v1 * B.b2.w;
    g3.x += v0 * B.a3.x + v1 * B.b3.x;
    g3.y += v0 * B.a3.y + v1 * B.b3.y;
    g3.z += v0 * B.a3.z + v1 * B.b3.z;
    g3.w += v0 * B.a3.w + v1 * B.b3.w;
}

__global__ void __launch_bounds__(LVA_THREADS, 1)
lva_fused_kernel(const float* __restrict__ x_in,
                 const float* __restrict__ A,
                 const float* __restrict__ b,
                 float* __restrict__ x_out,
                 int nprob)
{
    __shared__ __align__(16) float x_sm[LVA_N];
    __shared__ float b_sm[LVA_M];
    __shared__ __align__(16) float g_sm[LVA_NWARP * LVA_N];   // 32 KB
    __shared__ float red_sm[LVA_NWARP];
    __shared__ int   prob_sm;

    const int tid  = threadIdx.x;
    const int warp = tid >> 5;
    const int lane = tid & 31;

    for (;;) {
        __syncthreads();   // protect SMEM + prob_sm from previous problem
        if (tid == 0) prob_sm = atomicAdd(&lva_work_ctr, 1);
        __syncthreads();
        const int p = prob_sm;
        if (p >= nprob) return;

        const float* __restrict__ Ap = A + (size_t)p * LVA_M * LVA_N;

        x_sm[tid] = x_in[(size_t)p * LVA_N + tid];
        b_sm[tid] = b[(size_t)p * LVA_M + tid];
        __syncthreads();

        float4 xv0 = ((const float4*)x_sm)[lane];
        float4 xv1 = ((const float4*)x_sm)[lane + 32];
        float4 xv2 = ((const float4*)x_sm)[lane + 64];
        float4 xv3 = ((const float4*)x_sm)[lane + 96];

        for (int it = 0; it < LVA_ITERS; ++it) {
            float4 g0 = make_float4(0.f, 0.f, 0.f, 0.f);
            float4 g1 = g0, g2 = g0, g3 = g0;
            float vsum = 0.0f;

            Buf2 A0, A1;
            A0.load(Ap, warp, lane);

            // ping-pong over 16 bodies (2 rows each); no rotation MOVs.
            #pragma unroll 1
            for (int t = 0; t < 16; t += 2) {
                A1.load(Ap, warp + 32 * ((t + 1) & 15), lane);
                body2(A0, warp + 32 * t, b_sm,
                      xv0, xv1, xv2, xv3, g0, g1, g2, g3, vsum);
                A0.load(Ap, warp + 32 * ((t + 2) & 15), lane);
                body2(A1, warp + 32 * (t + 1), b_sm,
                      xv0, xv1, xv2, xv3, g0, g1, g2, g3, vsum);
            }

            // stage per-warp g partials (STS.128, conflict-free)
            float4* gp = (float4*)(g_sm + warp * LVA_N);
            gp[lane]      = g0;
            gp[lane + 32] = g1;
            gp[lane + 64] = g2;
            gp[lane + 96] = g3;
            if (lane == 0) red_sm[warp] = vsum;   // vsum is lane-uniform
            __syncthreads();

            // every thread: total violation (broadcast LDS, uniform branch)
            float vt0 = 0.0f, vt1 = 0.0f;
            #pragma unroll
            for (int w = 0; w < LVA_NWARP; w += 2) {
                vt0 += red_sm[w];
                vt1 += red_sm[w + 1];
            }
            if (vt0 + vt1 < LVA_DELTA) break;   // inactive BEFORE this update

            // column-tid g reduction across warps (two independent chains)
            float gta = 0.0f, gtb = 0.0f;
            #pragma unroll
            for (int w = 0; w < LVA_NWARP; w += 2) {
                gta += g_sm[w * LVA_N + tid];
                gtb += g_sm[(w + 1) * LVA_N + tid];
            }
            float gt = gta + gtb;

            float lr = LVA_ALPHA / (1.0f + LVA_SCALE * gt);
            float xn = x_sm[tid] - lr * gt;
            x_sm[tid] = xn > 0.0f ? xn : 0.0f;
            __syncthreads();

            xv0 = ((const float4*)x_sm)[lane];
            xv1 = ((const float4*)x_sm)[lane + 32];
            xv2 = ((const float4*)x_sm)[lane + 64];
            xv3 = ((const float4*)x_sm)[lane + 96];
        }

        x_out[(size_t)p * LVA_N + tid] = x_sm[tid];
    }
}

extern "C" void kernel_launch(void* const* d_in, const int* in_sizes, int n_in,
                              void* d_out, int out_size)
{
    const float* x = (const float*)d_in[0];   // [B,S,N]
    const float* A = (const float*)d_in[1];   // [B,S,M,N]
    const float* b = (const float*)d_in[2];   // [B,S,M]
    float* out = (float*)d_out;               // [B,S,N]

    int nprob = out_size / LVA_N;             // 256
    int ncta  = nprob < LVA_NCTA ? nprob : LVA_NCTA;

    lva_reset_kernel<<<1, 1>>>();
    lva_fused_kernel<<<ncta, LVA_THREADS>>>(x, A, b, out, nprob);
}